// round 1
// baseline (speedup 1.0000x reference)
#include <cuda_runtime.h>
#include <math.h>
#include <float.h>

// Problem constants
#define BB 64
#define HH 1024
#define VV 32000
#define TT 20
#define KK 1024          // all GEMMs have K = 1024 (D == H)
#define NBLK (VV / 64)   // 500 logits blocks

// ---------------------------------------------------------------------------
// Device scratch (no allocations allowed)
// ---------------------------------------------------------------------------
__device__ float g_h[2][BB * HH];      // ping-pong hidden state
__device__ float g_gi[BB * 3 * HH];    // x @ W_ih^T + b_ih
__device__ float g_gh[BB * 3 * HH];    // h @ W_hh^T + b_hh
__device__ float g_pval[BB * NBLK];    // per-block argmax partial values
__device__ int   g_pidx[BB * NBLK];    // per-block argmax partial indices
__device__ int   g_tok[BB];            // current token per batch row

__global__ void init_tok_kernel() {
    if (threadIdx.x < BB) g_tok[threadIdx.x] = 0;  // SOS = 0
}

// ---------------------------------------------------------------------------
// Tiled SGEMM: C[64 x N] = A[64 x 1024] @ W[N x 1024]^T + bias
// If emb != nullptr, row m of A is emb[g_tok[m], :] (embedding gather).
// Block computes a 64(batch) x 64(N) tile; 256 threads, 4x4 microtile, BK=16.
// ---------------------------------------------------------------------------
__global__ __launch_bounds__(256) void gemm64_kernel(
    const float* __restrict__ A, const float* __restrict__ emb,
    const float* __restrict__ W, const float* __restrict__ bias,
    float* __restrict__ C, int N)
{
    __shared__ float As[16][68];
    __shared__ float Bs[16][68];

    const int tid = threadIdx.x;
    const int tx = tid & 15, ty = tid >> 4;
    const int v0 = blockIdx.x * 64;
    const int lm = tid >> 2;            // 0..63  (row for loads)
    const int lk = (tid & 3) * 4;       // 0,4,8,12 (k offset for loads)

    const float* arow = emb ? (emb + (size_t)g_tok[lm] * HH)
                            : (A + (size_t)lm * KK);
    const float* wrow = W + (size_t)(v0 + lm) * KK;

    float acc[4][4] = {};

    for (int k0 = 0; k0 < KK; k0 += 16) {
        float4 av = *(const float4*)(arow + k0 + lk);
        float4 wv = *(const float4*)(wrow + k0 + lk);
        As[lk + 0][lm] = av.x; As[lk + 1][lm] = av.y;
        As[lk + 2][lm] = av.z; As[lk + 3][lm] = av.w;
        Bs[lk + 0][lm] = wv.x; Bs[lk + 1][lm] = wv.y;
        Bs[lk + 2][lm] = wv.z; Bs[lk + 3][lm] = wv.w;
        __syncthreads();
        #pragma unroll
        for (int kk = 0; kk < 16; kk++) {
            float4 a = *(const float4*)&As[kk][ty * 4];
            float4 b = *(const float4*)&Bs[kk][tx * 4];
            float af[4] = {a.x, a.y, a.z, a.w};
            float bf[4] = {b.x, b.y, b.z, b.w};
            #pragma unroll
            for (int i = 0; i < 4; i++)
                #pragma unroll
                for (int j = 0; j < 4; j++)
                    acc[i][j] = fmaf(af[i], bf[j], acc[i][j]);
        }
        __syncthreads();
    }

    #pragma unroll
    for (int i = 0; i < 4; i++) {
        int m = ty * 4 + i;
        #pragma unroll
        for (int j = 0; j < 4; j++) {
            int n = v0 + tx * 4 + j;
            C[(size_t)m * N + n] = acc[i][j] + bias[n];
        }
    }
}

// ---------------------------------------------------------------------------
// GRU gate math (PyTorch convention), biases already folded into gi/gh.
// ---------------------------------------------------------------------------
__global__ void gru_gate_kernel(const float* __restrict__ hin,
                                float* __restrict__ hout)
{
    int idx = blockIdx.x * blockDim.x + threadIdx.x;
    if (idx >= BB * HH) return;
    int b = idx >> 10, j = idx & 1023;
    const float* gi = g_gi + (size_t)b * 3 * HH;
    const float* gh = g_gh + (size_t)b * 3 * HH;
    float r = 1.f / (1.f + expf(-(gi[j] + gh[j])));
    float z = 1.f / (1.f + expf(-(gi[HH + j] + gh[HH + j])));
    float n = tanhf(gi[2 * HH + j] + r * gh[2 * HH + j]);
    hout[idx] = (1.f - z) * n + z * hin[idx];
}

// ---------------------------------------------------------------------------
// Logits tile (64 batch x 64 vocab) + fused per-block argmax partials.
// Same SGEMM core as gemm64_kernel; 500 blocks cover V=32000.
// ---------------------------------------------------------------------------
__global__ __launch_bounds__(256) void logits_argmax_kernel(
    const float* __restrict__ A, const float* __restrict__ W,
    const float* __restrict__ bias)
{
    __shared__ float As[16][68];
    __shared__ float Bs[16][68];
    __shared__ float rv[64][16];
    __shared__ int   ri[64][16];

    const int tid = threadIdx.x;
    const int tx = tid & 15, ty = tid >> 4;
    const int v0 = blockIdx.x * 64;
    const int lm = tid >> 2;
    const int lk = (tid & 3) * 4;

    const float* arow = A + (size_t)lm * KK;
    const float* wrow = W + (size_t)(v0 + lm) * KK;

    float acc[4][4] = {};

    for (int k0 = 0; k0 < KK; k0 += 16) {
        float4 av = *(const float4*)(arow + k0 + lk);
        float4 wv = *(const float4*)(wrow + k0 + lk);
        As[lk + 0][lm] = av.x; As[lk + 1][lm] = av.y;
        As[lk + 2][lm] = av.z; As[lk + 3][lm] = av.w;
        Bs[lk + 0][lm] = wv.x; Bs[lk + 1][lm] = wv.y;
        Bs[lk + 2][lm] = wv.z; Bs[lk + 3][lm] = wv.w;
        __syncthreads();
        #pragma unroll
        for (int kk = 0; kk < 16; kk++) {
            float4 a = *(const float4*)&As[kk][ty * 4];
            float4 b = *(const float4*)&Bs[kk][tx * 4];
            float af[4] = {a.x, a.y, a.z, a.w};
            float bf[4] = {b.x, b.y, b.z, b.w};
            #pragma unroll
            for (int i = 0; i < 4; i++)
                #pragma unroll
                for (int j = 0; j < 4; j++)
                    acc[i][j] = fmaf(af[i], bf[j], acc[i][j]);
        }
        __syncthreads();
    }

    // Per-thread argmax over its 4 vocab columns, for each of its 4 batch rows.
    #pragma unroll
    for (int i = 0; i < 4; i++) {
        int m = ty * 4 + i;
        float best = -FLT_MAX; int bidx = VV;
        #pragma unroll
        for (int j = 0; j < 4; j++) {
            int v = v0 + tx * 4 + j;
            float val = acc[i][j] + bias[v];
            if (val > best) { best = val; bidx = v; }   // first-max wins
        }
        rv[m][tx] = best; ri[m][tx] = bidx;
    }
    __syncthreads();

    if (tid < 64) {
        float best = rv[tid][0]; int bi = ri[tid][0];
        #pragma unroll
        for (int t = 1; t < 16; t++) {
            float v = rv[tid][t]; int idx = ri[tid][t];
            if (v > best || (v == best && idx < bi)) { best = v; bi = idx; }
        }
        g_pval[(size_t)tid * NBLK + blockIdx.x] = best;
        g_pidx[(size_t)tid * NBLK + blockIdx.x] = bi;
    }
}

// ---------------------------------------------------------------------------
// Reduce the 500 partials per batch row -> token; write token to d_out.
// ---------------------------------------------------------------------------
__global__ __launch_bounds__(256) void finalize_kernel(int t, float* __restrict__ out)
{
    int b = blockIdx.x;
    __shared__ float sv[256];
    __shared__ int   si[256];
    float best = -FLT_MAX; int bi = VV;
    for (int i = threadIdx.x; i < NBLK; i += 256) {
        float v = g_pval[(size_t)b * NBLK + i];
        int idx  = g_pidx[(size_t)b * NBLK + i];
        if (v > best || (v == best && idx < bi)) { best = v; bi = idx; }
    }
    sv[threadIdx.x] = best; si[threadIdx.x] = bi;
    __syncthreads();
    for (int s = 128; s > 0; s >>= 1) {
        if (threadIdx.x < s) {
            float v = sv[threadIdx.x + s]; int idx = si[threadIdx.x + s];
            if (v > sv[threadIdx.x] ||
                (v == sv[threadIdx.x] && idx < si[threadIdx.x])) {
                sv[threadIdx.x] = v; si[threadIdx.x] = idx;
            }
        }
        __syncthreads();
    }
    if (threadIdx.x == 0) {
        g_tok[b] = si[0];
        out[b * TT + t] = (float)si[0];   // toks.T layout: [B, T]
    }
}

// ---------------------------------------------------------------------------
// Copy final hidden state (after step T-1 it lives in g_h[0]) to d_out tail.
// ---------------------------------------------------------------------------
__global__ void copy_h_kernel(float* __restrict__ out, int out_size)
{
    int i = blockIdx.x * blockDim.x + threadIdx.x;
    if (i < BB * HH && (BB * TT + i) < out_size)
        out[BB * TT + i] = g_h[0][i];
}

// ---------------------------------------------------------------------------
extern "C" void kernel_launch(void* const* d_in, const int* in_sizes, int n_in,
                              void* d_out, int out_size)
{
    const float* latent = (const float*)d_in[0];
    const float* W_proj = (const float*)d_in[1];
    const float* b_proj = (const float*)d_in[2];
    const float* emb    = (const float*)d_in[3];
    const float* W_ih   = (const float*)d_in[4];
    const float* b_ih   = (const float*)d_in[5];
    const float* W_hh   = (const float*)d_in[6];
    const float* b_hh   = (const float*)d_in[7];
    const float* W_out  = (const float*)d_in[8];
    const float* b_out  = (const float*)d_in[9];
    float* out = (float*)d_out;

    // Resolve device-symbol scratch addresses (host API, not a stream op —
    // safe under graph capture; no allocation).
    float *p_h = nullptr, *p_gi = nullptr, *p_gh = nullptr;
    cudaGetSymbolAddress((void**)&p_h,  g_h);
    cudaGetSymbolAddress((void**)&p_gi, g_gi);
    cudaGetSymbolAddress((void**)&p_gh, g_gh);

    init_tok_kernel<<<1, 64>>>();

    // h0 = latent @ W_proj^T + b_proj  -> g_h[0]
    gemm64_kernel<<<HH / 64, 256>>>(latent, nullptr, W_proj, b_proj, p_h, HH);

    for (int t = 0; t < TT; t++) {
        const float* hin = p_h + (t & 1) * (BB * HH);
        float*       hout = p_h + ((t + 1) & 1) * (BB * HH);

        // gi = emb[tok] @ W_ih^T + b_ih ;  gh = h @ W_hh^T + b_hh
        gemm64_kernel<<<3 * HH / 64, 256>>>(nullptr, emb, W_ih, b_ih, p_gi, 3 * HH);
        gemm64_kernel<<<3 * HH / 64, 256>>>(hin, nullptr, W_hh, b_hh, p_gh, 3 * HH);
        gru_gate_kernel<<<(BB * HH + 255) / 256, 256>>>(hin, hout);

        // logits = h_new @ W_out^T + b_out ; fused blockwise argmax
        logits_argmax_kernel<<<NBLK, 256>>>(hout, W_out, b_out);
        finalize_kernel<<<BB, 256>>>(t, out);
    }

    copy_h_kernel<<<(BB * HH + 255) / 256, 256>>>(out, out_size);
}

// round 2
// speedup vs baseline: 1.6988x; 1.6988x over previous
#include <cuda_runtime.h>
#include <math.h>
#include <float.h>

// Problem constants
#define BB 64
#define HH 1024
#define VV 32000
#define TT 20
#define KK 1024
#define NBLK (VV / 64)   // 500 logits blocks
#define GRU_KC 4         // split-K chunks for GRU gemms
#define H0_KC 8          // split-K chunks for h0 projection

// ---------------------------------------------------------------------------
// Device scratch
// ---------------------------------------------------------------------------
__device__ float g_h[2][BB * HH];              // ping-pong hidden state
__device__ float g_part[GRU_KC][BB * 6 * HH];  // split-K partials: [gi(3H) | gh(3H)]
__device__ float g_h0part[H0_KC][BB * HH];     // split-K partials for h0
__device__ float g_pval[BB * NBLK];
__device__ int   g_pidx[BB * NBLK];
__device__ int   g_tok[BB];

__global__ void init_tok_kernel() {
    if (threadIdx.x < BB) g_tok[threadIdx.x] = 0;  // SOS = 0
}

// ---------------------------------------------------------------------------
// Double-buffered 64x64 SGEMM core (BK=16, 256 threads, 4x4 microtile).
// Computes acc[4][4] for rows ty*4.. and cols tx*4.. of a 64x64 tile,
// iterating k over [kbase, kbase+klen).
// ---------------------------------------------------------------------------
#define GEMM_CORE(arow, wrow, kbase, klen)                                     \
    float acc[4][4] = {};                                                      \
    {                                                                          \
        float4 av = *(const float4*)((arow) + (kbase) + lk);                   \
        float4 wv = *(const float4*)((wrow) + (kbase) + lk);                   \
        As[0][lk + 0][lm] = av.x; As[0][lk + 1][lm] = av.y;                    \
        As[0][lk + 2][lm] = av.z; As[0][lk + 3][lm] = av.w;                    \
        Bs[0][lk + 0][lm] = wv.x; Bs[0][lk + 1][lm] = wv.y;                    \
        Bs[0][lk + 2][lm] = wv.z; Bs[0][lk + 3][lm] = wv.w;                    \
    }                                                                          \
    __syncthreads();                                                           \
    int buf = 0;                                                               \
    for (int k0 = 16; k0 <= (klen); k0 += 16) {                                \
        float4 av2, wv2;                                                       \
        const bool more = (k0 < (klen));                                       \
        if (more) {                                                            \
            av2 = *(const float4*)((arow) + (kbase) + k0 + lk);                \
            wv2 = *(const float4*)((wrow) + (kbase) + k0 + lk);                \
        }                                                                      \
        _Pragma("unroll")                                                      \
        for (int kk = 0; kk < 16; kk++) {                                      \
            float4 a = *(const float4*)&As[buf][kk][ty * 4];                   \
            float4 b = *(const float4*)&Bs[buf][kk][tx * 4];                   \
            float af[4] = {a.x, a.y, a.z, a.w};                                \
            float bf[4] = {b.x, b.y, b.z, b.w};                                \
            _Pragma("unroll")                                                  \
            for (int i = 0; i < 4; i++)                                        \
                _Pragma("unroll")                                              \
                for (int j = 0; j < 4; j++)                                    \
                    acc[i][j] = fmaf(af[i], bf[j], acc[i][j]);                 \
        }                                                                      \
        if (more) {                                                            \
            As[buf ^ 1][lk + 0][lm] = av2.x; As[buf ^ 1][lk + 1][lm] = av2.y;  \
            As[buf ^ 1][lk + 2][lm] = av2.z; As[buf ^ 1][lk + 3][lm] = av2.w;  \
            Bs[buf ^ 1][lk + 0][lm] = wv2.x; Bs[buf ^ 1][lk + 1][lm] = wv2.y;  \
            Bs[buf ^ 1][lk + 2][lm] = wv2.z; Bs[buf ^ 1][lk + 3][lm] = wv2.w;  \
        }                                                                      \
        __syncthreads();                                                       \
        buf ^= 1;                                                              \
    }

#define GEMM_PROLOGUE                                                          \
    __shared__ float As[2][16][68];                                            \
    __shared__ float Bs[2][16][68];                                            \
    const int tid = threadIdx.x;                                               \
    const int tx = tid & 15, ty = tid >> 4;                                    \
    const int lm = tid >> 2;                                                   \
    const int lk = (tid & 3) * 4;

// ---------------------------------------------------------------------------
// Fused GRU input+hidden GEMM with split-K.
// blockIdx.x in [0,96): tiles 0..47 -> gi (A = emb[tok]), 48..95 -> gh (A = h).
// blockIdx.y in [0,4): K-chunk of 256. Partials -> g_part.
// ---------------------------------------------------------------------------
__global__ __launch_bounds__(256) void gru_gemm_kernel(
    const float* __restrict__ emb, const float* __restrict__ W_ih,
    const float* __restrict__ W_hh, const float* __restrict__ hin)
{
    GEMM_PROLOGUE
    const int tile = blockIdx.x;
    const int kc = blockIdx.y;
    const bool is_gi = tile < 48;
    const int n0 = (tile & 47) * 64;          // tile%48 (48 = 0b110000; use mod)
    const int n0f = (tile % 48) * 64;
    (void)n0;
    const float* W = is_gi ? W_ih : W_hh;
    const float* arow = is_gi ? (emb + (size_t)g_tok[lm] * HH)
                              : (hin + (size_t)lm * HH);
    const float* wrow = W + (size_t)(n0f + lm) * KK;
    const int kbase = kc * (KK / GRU_KC);

    GEMM_CORE(arow, wrow, kbase, (KK / GRU_KC))

    float* outp = g_part[kc] + (is_gi ? 0 : 3 * HH);
    #pragma unroll
    for (int i = 0; i < 4; i++) {
        int m = ty * 4 + i;
        #pragma unroll
        for (int j = 0; j < 4; j++)
            outp[(size_t)m * 6 * HH + n0f + tx * 4 + j] = acc[i][j];
    }
}

// ---------------------------------------------------------------------------
// GRU gate math: reduce split-K partials, add biases, apply gates.
// ---------------------------------------------------------------------------
__global__ void gru_gate_kernel(const float* __restrict__ hin,
                                float* __restrict__ hout,
                                const float* __restrict__ b_ih,
                                const float* __restrict__ b_hh)
{
    int idx = blockIdx.x * blockDim.x + threadIdx.x;
    if (idx >= BB * HH) return;
    int b = idx >> 10, j = idx & 1023;
    float ir = b_ih[j], iz = b_ih[HH + j], in_ = b_ih[2 * HH + j];
    float hr = b_hh[j], hz = b_hh[HH + j], hn = b_hh[2 * HH + j];
    #pragma unroll
    for (int c = 0; c < GRU_KC; c++) {
        const float* p = g_part[c] + (size_t)b * 6 * HH;
        ir += p[j];          iz += p[HH + j];          in_ += p[2 * HH + j];
        hr += p[3 * HH + j]; hz += p[4 * HH + j];      hn  += p[5 * HH + j];
    }
    float r = 1.f / (1.f + expf(-(ir + hr)));
    float z = 1.f / (1.f + expf(-(iz + hz)));
    float n = tanhf(in_ + r * hn);
    hout[idx] = (1.f - z) * n + z * hin[idx];
}

// ---------------------------------------------------------------------------
// h0 projection with split-K: partials -> g_h0part
// ---------------------------------------------------------------------------
__global__ __launch_bounds__(256) void h0_gemm_kernel(
    const float* __restrict__ latent, const float* __restrict__ W_proj)
{
    GEMM_PROLOGUE
    const int n0 = blockIdx.x * 64;
    const int kc = blockIdx.y;
    const float* arow = latent + (size_t)lm * KK;
    const float* wrow = W_proj + (size_t)(n0 + lm) * KK;
    const int kbase = kc * (KK / H0_KC);

    GEMM_CORE(arow, wrow, kbase, (KK / H0_KC))

    #pragma unroll
    for (int i = 0; i < 4; i++) {
        int m = ty * 4 + i;
        #pragma unroll
        for (int j = 0; j < 4; j++)
            g_h0part[kc][(size_t)m * HH + n0 + tx * 4 + j] = acc[i][j];
    }
}

__global__ void h0_reduce_kernel(float* __restrict__ h,
                                 const float* __restrict__ b_proj)
{
    int idx = blockIdx.x * blockDim.x + threadIdx.x;
    if (idx >= BB * HH) return;
    int j = idx & 1023;
    float s = b_proj[j];
    #pragma unroll
    for (int c = 0; c < H0_KC; c++) s += g_h0part[c][idx];
    h[idx] = s;
}

// ---------------------------------------------------------------------------
// Logits tile (64x64) + fused per-block argmax partials. 500 blocks.
// ---------------------------------------------------------------------------
__global__ __launch_bounds__(256) void logits_argmax_kernel(
    const float* __restrict__ A, const float* __restrict__ W,
    const float* __restrict__ bias)
{
    GEMM_PROLOGUE
    __shared__ float rv[64][16];
    __shared__ int   ri[64][16];
    const int v0 = blockIdx.x * 64;
    const float* arow = A + (size_t)lm * KK;
    const float* wrow = W + (size_t)(v0 + lm) * KK;

    GEMM_CORE(arow, wrow, 0, KK)

    #pragma unroll
    for (int i = 0; i < 4; i++) {
        int m = ty * 4 + i;
        float best = -FLT_MAX; int bidx = VV;
        #pragma unroll
        for (int j = 0; j < 4; j++) {
            int v = v0 + tx * 4 + j;
            float val = acc[i][j] + bias[v];
            if (val > best) { best = val; bidx = v; }   // first-max wins
        }
        rv[m][tx] = best; ri[m][tx] = bidx;
    }
    __syncthreads();

    if (tid < 64) {
        float best = rv[tid][0]; int bi = ri[tid][0];
        #pragma unroll
        for (int t = 1; t < 16; t++) {
            float v = rv[tid][t]; int idx = ri[tid][t];
            if (v > best || (v == best && idx < bi)) { best = v; bi = idx; }
        }
        g_pval[(size_t)tid * NBLK + blockIdx.x] = best;
        g_pidx[(size_t)tid * NBLK + blockIdx.x] = bi;
    }
}

// ---------------------------------------------------------------------------
// Reduce the 500 partials per batch row -> token.
// ---------------------------------------------------------------------------
__global__ __launch_bounds__(256) void finalize_kernel(int t, float* __restrict__ out)
{
    int b = blockIdx.x;
    __shared__ float sv[256];
    __shared__ int   si[256];
    float best = -FLT_MAX; int bi = VV;
    for (int i = threadIdx.x; i < NBLK; i += 256) {
        float v = g_pval[(size_t)b * NBLK + i];
        int idx  = g_pidx[(size_t)b * NBLK + i];
        if (v > best || (v == best && idx < bi)) { best = v; bi = idx; }
    }
    sv[threadIdx.x] = best; si[threadIdx.x] = bi;
    __syncthreads();
    for (int s = 128; s > 0; s >>= 1) {
        if (threadIdx.x < s) {
            float v = sv[threadIdx.x + s]; int idx = si[threadIdx.x + s];
            if (v > sv[threadIdx.x] ||
                (v == sv[threadIdx.x] && idx < si[threadIdx.x])) {
                sv[threadIdx.x] = v; si[threadIdx.x] = idx;
            }
        }
        __syncthreads();
    }
    if (threadIdx.x == 0) {
        g_tok[b] = si[0];
        out[b * TT + t] = (float)si[0];
    }
}

__global__ void copy_h_kernel(float* __restrict__ out, int out_size)
{
    int i = blockIdx.x * blockDim.x + threadIdx.x;
    if (i < BB * HH && (BB * TT + i) < out_size)
        out[BB * TT + i] = g_h[0][i];
}

// ---------------------------------------------------------------------------
extern "C" void kernel_launch(void* const* d_in, const int* in_sizes, int n_in,
                              void* d_out, int out_size)
{
    const float* latent = (const float*)d_in[0];
    const float* W_proj = (const float*)d_in[1];
    const float* b_proj = (const float*)d_in[2];
    const float* emb    = (const float*)d_in[3];
    const float* W_ih   = (const float*)d_in[4];
    const float* b_ih   = (const float*)d_in[5];
    const float* W_hh   = (const float*)d_in[6];
    const float* b_hh   = (const float*)d_in[7];
    const float* W_out  = (const float*)d_in[8];
    const float* b_out  = (const float*)d_in[9];
    float* out = (float*)d_out;

    float* p_h = nullptr;
    cudaGetSymbolAddress((void**)&p_h, g_h);

    init_tok_kernel<<<1, 64>>>();

    // h0 = latent @ W_proj^T + b_proj
    h0_gemm_kernel<<<dim3(HH / 64, H0_KC), 256>>>(latent, W_proj);
    h0_reduce_kernel<<<(BB * HH + 255) / 256, 256>>>(p_h, b_proj);

    for (int t = 0; t < TT; t++) {
        const float* hin = p_h + (t & 1) * (BB * HH);
        float*       hout = p_h + ((t + 1) & 1) * (BB * HH);

        gru_gemm_kernel<<<dim3(96, GRU_KC), 256>>>(emb, W_ih, W_hh, hin);
        gru_gate_kernel<<<(BB * HH + 255) / 256, 256>>>(hin, hout, b_ih, b_hh);

        logits_argmax_kernel<<<NBLK, 256>>>(hout, W_out, b_out);
        finalize_kernel<<<BB, 256>>>(t, out);
    }

    copy_h_kernel<<<(BB * HH + 255) / 256, 256>>>(out, out_size);
}